// round 16
// baseline (speedup 1.0000x reference)
#include <cuda_runtime.h>
#include <cstdint>

#define NN 50000
#define C 128
#define EE 600000
#define NB_BLK 391            // (NN+127)/128
#define FRAG_U32 (NB_BLK * 16384)
#define SCAN_NB 196           // (NN + 255) / 256

// ---------------- device scratch ----------------
__device__ float    g_A[NN * C];
__device__ float    g_B[NN * C];
__device__ float    g_deg[NN];
__device__ unsigned g_Xf[FRAG_U32];      // X in A-fragment order
__device__ unsigned g_Hf[FRAG_U32];      // H in A-fragment order
__device__ unsigned g_Rf[FRAG_U32];      // (s*R + deg*c) in A-fragment order
__device__ unsigned g_Wf[2][2][16384];   // AB weights, B-fragment order [layer][half]
__device__ unsigned g_Wbf[2][16384];     // OUT weights, B-fragment order [layer]
__device__ int      g_cnt[NN];
__device__ int      g_rowp[NN + 1];
__device__ int      g_offw[NN];
__device__ int      g_bsum[256];
__device__ int      g_boff[256];
__device__ int      g_csr[EE];
__device__ int      g_is64;
__device__ float    g_s[2][C];
__device__ float    g_c[2][C];

// ---------------- helpers ----------------
__device__ __forceinline__ unsigned pack_bf(float hi, float lo) {
    unsigned r; asm("cvt.rn.bf16x2.f32 %0, %1, %2;" : "=r"(r) : "f"(hi), "f"(lo)); return r;
}
__device__ __forceinline__ void mma16(float* c, unsigned a0, unsigned a1, unsigned a2, unsigned a3,
                                      unsigned b0, unsigned b1) {
    asm volatile("mma.sync.aligned.m16n8k16.row.col.f32.bf16.bf16.f32 "
                 "{%0,%1,%2,%3},{%4,%5,%6,%7},{%8,%9},{%0,%1,%2,%3};"
                 : "+f"(c[0]), "+f"(c[1]), "+f"(c[2]), "+f"(c[3])
                 : "r"(a0), "r"(a1), "r"(a2), "r"(a3), "r"(b0), "r"(b1));
}
__device__ __forceinline__ void split2(float x0, float x1, unsigned& h, unsigned& l) {
    h = pack_bf(x1, x0);
    float lo0 = __uint_as_float(h << 16);
    float hi1 = __uint_as_float(h & 0xFFFF0000u);
    l = pack_bf(x1 - hi1, x0 - lo0);
}
__device__ __forceinline__ int edge_val(const void* ei, int idx) {
    if (g_is64) return (int)((const long long*)ei)[idx];
    return ((const int*)ei)[idx];
}
// B(W)-fragment flat u32 offset (uint4 granule) for row, pair-in-chunk s, chunk kc
__device__ __forceinline__ int frag_base(int row, int kc, int s) {
    int n0g = row >> 5, q = (row >> 3) & 3, g8 = row & 7, tig = s & 3;
    return ((((kc * 4 + n0g) * 4 + q) * 8 + g8) * 4 + tig) * 4;
}
// A-fragment u32 index for the hi(p=0)/lo(p=1) u32 of (row, pair P)
__device__ __forceinline__ int a_off(int row, int P, int p) {
    int nb = row >> 7, r = row & 127;
    int m0g = r >> 6, rr = r & 63, mt = rr >> 4, g = rr & 15;
    int gid = g & 7, plus8 = g >> 3;
    int kc = P >> 3, s = P & 7, tig = s & 3, halfsel = s >> 2;
    int lane = gid * 4 + tig;
    int u4 = (((((nb * 8) + kc) * 2 + m0g) * 4 + mt) * 2 + p) * 32 + lane;
    return u4 * 4 + halfsel * 2 + plus8;
}

// ---------------- prep: zero cnt + fragment-order weights + BN affine ------
__global__ void prep_all(const float* __restrict__ w1a, const float* __restrict__ w2a,
                         const float* __restrict__ w1b, const float* __restrict__ w2b,
                         const float* g1, const float* be1, const float* rm1, const float* rv1,
                         const float* g2, const float* be2, const float* rm2, const float* rv2) {
    int gid = blockIdx.x * blockDim.x + threadIdx.x;   // 65536
    if (gid < NN) g_cnt[gid] = 0;
    if (gid < 2 * 256 * 64) {    // Wc pairs: layer, r(0..255), p(0..63)
        int layer = gid >> 14;
        int r = (gid >> 6) & 255;
        int p = gid & 63;
        const float* wa = layer ? w2a : w1a;
        int k0 = 2 * p, k1 = 2 * p + 1;
        float v0, v1;
        if (r < C) {
            v0 = wa[r * 2 * C + k0] - wa[r * 2 * C + C + k0];
            v1 = wa[r * 2 * C + k1] - wa[r * 2 * C + C + k1];
        } else {
            v0 = wa[(r - C) * 2 * C + C + k0];
            v1 = wa[(r - C) * 2 * C + C + k1];
        }
        unsigned h, l; split2(v0, v1, h, l);
        int half = r >> 7, row = r & 127;
        int kc = p >> 3, s = p & 7;
        int base = frag_base(row, kc, s);
        int chi = s >> 2;
        g_Wf[layer][half][base + chi] = h;
        g_Wf[layer][half][base + 2 + chi] = l;
    }
    if (gid < 2 * 128 * 64) {    // Wb pairs
        int layer = gid >> 13;
        int r = (gid >> 6) & 127;
        int p = gid & 63;
        const float* wb = layer ? w2b : w1b;
        float v0 = wb[r * C + 2 * p], v1 = wb[r * C + 2 * p + 1];
        unsigned h, l; split2(v0, v1, h, l);
        int kc = p >> 3, s = p & 7;
        int base = frag_base(r, kc, s);
        int chi = s >> 2;
        g_Wbf[layer][base + chi] = h;
        g_Wbf[layer][base + 2 + chi] = l;
    }
    if (gid < 256) {
        int layer = gid >> 7;
        int k = gid & 127;
        const float* g  = layer ? g2  : g1;
        const float* be = layer ? be2 : be1;
        const float* rm = layer ? rm2 : rm1;
        const float* rv = layer ? rv2 : rv1;
        float s = g[k] * rsqrtf(rv[k] + 1e-5f);
        g_s[layer][k] = s;
        g_c[layer][k] = be[k] - rm[k] * s;
    }
}

// ---------------- X -> A-fragment order ------------------------------------
// one thread per (nb, kc, m0g, mt, lane): writes hi+lo uint4
__global__ void conv_x(const float* __restrict__ x) {
    int t = blockIdx.x * blockDim.x + threadIdx.x;   // NB_BLK * 2048
    if (t >= NB_BLK * 2048) return;
    int lane = t & 31;
    int mt   = (t >> 5) & 3;
    int m0g  = (t >> 7) & 1;
    int kc   = (t >> 8) & 7;
    int nb   = t >> 11;
    int gid = lane >> 2, tig = lane & 3;
    int row = nb * 128 + m0g * 64 + mt * 16 + gid;
    int row2 = row + 8;
    int c0 = 2 * (kc * 8 + tig);        // element col of pair k0
    int c1 = 2 * (kc * 8 + 4 + tig);    // element col of pair k1
    float2 a01 = make_float2(0.f, 0.f), a23 = make_float2(0.f, 0.f);
    float2 b01 = make_float2(0.f, 0.f), b23 = make_float2(0.f, 0.f);
    if (row < NN) {
        a01 = *(const float2*)(x + (size_t)row * C + c0);
        a23 = *(const float2*)(x + (size_t)row * C + c1);
    }
    if (row2 < NN) {
        b01 = *(const float2*)(x + (size_t)row2 * C + c0);
        b23 = *(const float2*)(x + (size_t)row2 * C + c1);
    }
    uint4 hi, lo;
    split2(a01.x, a01.y, hi.x, lo.x);   // (row,  k0)
    split2(b01.x, b01.y, hi.y, lo.y);   // (row+8,k0)
    split2(a23.x, a23.y, hi.z, lo.z);   // (row,  k1)
    split2(b23.x, b23.y, hi.w, lo.w);   // (row+8,k1)
    int u4 = (((((nb * 8) + kc) * 2 + m0g) * 4 + mt) * 2) * 32 + lane;
    ((uint4*)g_Xf)[u4] = hi;
    ((uint4*)g_Xf)[u4 + 32] = lo;
}

__global__ void detect_kernel(const void* __restrict__ ei) {
    int t = threadIdx.x;
    int bad = 0;
    if (t < 16) {
        long long v = ((const long long*)ei)[t];
        bad = (v < 0) || (v >= (long long)NN);
    }
    unsigned m = __ballot_sync(0xFFFFFFFFu, bad);
    if (t == 0) g_is64 = (m == 0);
}

__global__ void hist_kernel(const void* __restrict__ ei) {
    int e = blockIdx.x * blockDim.x + threadIdx.x;
    if (e >= EE) return;
    atomicAdd(&g_cnt[edge_val(ei, EE + e)], 1);
}

__global__ void scan_local() {
    __shared__ int sm[256];
    int t = threadIdx.x;
    int i = blockIdx.x * 256 + t;
    int v = (i < NN) ? g_cnt[i] : 0;
    sm[t] = v;
    __syncthreads();
#pragma unroll
    for (int off = 1; off < 256; off <<= 1) {
        int u = (t >= off) ? sm[t - off] : 0;
        __syncthreads();
        sm[t] += u;
        __syncthreads();
    }
    if (i < NN) g_rowp[i] = sm[t] - v;
    if (t == 255) g_bsum[blockIdx.x] = sm[255];
}

__global__ void scan_bsum() {
    __shared__ int sm[256];
    int t = threadIdx.x;
    int v = (t < SCAN_NB) ? g_bsum[t] : 0;
    sm[t] = v;
    __syncthreads();
#pragma unroll
    for (int off = 1; off < 256; off <<= 1) {
        int u = (t >= off) ? sm[t - off] : 0;
        __syncthreads();
        sm[t] += u;
        __syncthreads();
    }
    g_boff[t] = sm[t] - v;
    if (t == 255) g_rowp[NN] = sm[255];
}

__global__ void scan_add() {
    int i = blockIdx.x * 256 + threadIdx.x;
    if (i >= NN) return;
    int r = g_rowp[i] + g_boff[blockIdx.x];
    g_rowp[i] = r;
    g_offw[i] = r;
}

__global__ void scatter_kernel(const void* __restrict__ ei) {
    int e = blockIdx.x * blockDim.x + threadIdx.x;
    if (e >= EE) return;
    int d = edge_val(ei, EE + e);
    int s = edge_val(ei, e);
    int p = atomicAdd(&g_offw[d], 1);
    g_csr[p] = s;
}

// ---------------- bf16 MMA GEMM: pure LDG fragment streams -----------------
// NO smem staging, NO barriers, NO ldmatrix: A and W both pre-permuted in gmem.
// mode 0: AB (out g_A with ba / g_B, by grid.y); mode 1: OUT plain -> Og (+deg*bias);
// mode 2: OUT fused relu+L2norm -> g_Hf (fragment order)
__global__ __launch_bounds__(256, 2) void mma_gemm(
    const unsigned* __restrict__ Af, const unsigned* __restrict__ Wfrag,
    const float* __restrict__ bias, float* __restrict__ Og, int mode)
{
    __shared__ float rowss[128];

    int tid = threadIdx.x;
    int i0 = blockIdx.x * 128;
    int half = blockIdx.y;

    if (tid < 128) rowss[tid] = 0.f;
    if (mode == 2) __syncthreads();

    int wid = tid >> 5, lane = tid & 31;
    int gid = lane >> 2, tig = lane & 3;
    int m0 = (wid & 1) * 64;
    int n0g = wid >> 1;
    int n0 = n0g * 32;

    // fragment streams (uint4 granule)
    const uint4* af = (const uint4*)Af + (size_t)blockIdx.x * 4096 + (wid & 1) * 256 + lane;
    const uint4* wf = (const uint4*)(Wfrag + (mode == 0 ? half * 16384 : 0))
                      + (n0g * 128 + gid * 4 + tig);

    float acc[4][4][4];
#pragma unroll
    for (int a = 0; a < 4; a++)
#pragma unroll
        for (int b = 0; b < 4; b++)
#pragma unroll
            for (int d = 0; d < 4; d++) acc[a][b][d] = 0.f;

#pragma unroll
    for (int kc = 0; kc < 8; kc++) {
        const uint4* ak = af + kc * 512;
        // B fragments: 4 coalesced LDG.128
        unsigned bh0[4], bh1[4], bl0[4], bl1[4];
#pragma unroll
        for (int q = 0; q < 4; q++) {
            uint4 v = wf[kc * 512 + q * 32];
            bh0[q] = v.x; bh1[q] = v.y; bl0[q] = v.z; bl1[q] = v.w;
        }
#pragma unroll
        for (int mt = 0; mt < 4; mt++) {
            uint4 hv = ak[mt * 64];
            uint4 lv = ak[mt * 64 + 32];
#pragma unroll
            for (int nt = 0; nt < 4; nt++) {
                mma16(acc[mt][nt], hv.x, hv.y, hv.z, hv.w, bh0[nt], bh1[nt]);
                mma16(acc[mt][nt], hv.x, hv.y, hv.z, hv.w, bl0[nt], bl1[nt]);
                mma16(acc[mt][nt], lv.x, lv.y, lv.z, lv.w, bh0[nt], bh1[nt]);
            }
        }
    }

    // --- epilogue ---
    if (mode == 0) {
        float* outp = half ? g_B : g_A;
#pragma unroll
        for (int mt = 0; mt < 4; mt++) {
            int r0 = i0 + m0 + mt * 16 + gid;
            int r1 = r0 + 8;
#pragma unroll
            for (int nt = 0; nt < 4; nt++) {
                int col = n0 + nt * 8 + 2 * tig;
                float* cc = acc[mt][nt];
                float b0 = 0.f, b1 = 0.f;
                if (half == 0) { b0 = bias[col]; b1 = bias[col + 1]; }
                if (r0 < NN) { float2 v = {cc[0] + b0, cc[1] + b1}; *(float2*)(outp + (size_t)r0 * C + col) = v; }
                if (r1 < NN) { float2 v = {cc[2] + b0, cc[3] + b1}; *(float2*)(outp + (size_t)r1 * C + col) = v; }
            }
        }
    } else if (mode == 1) {
#pragma unroll
        for (int mt = 0; mt < 4; mt++) {
            int r0 = i0 + m0 + mt * 16 + gid;
            int r1 = r0 + 8;
            float d0 = (r0 < NN) ? g_deg[r0] : 0.f;
            float d1 = (r1 < NN) ? g_deg[r1] : 0.f;
#pragma unroll
            for (int nt = 0; nt < 4; nt++) {
                int col = n0 + nt * 8 + 2 * tig;
                float* cc = acc[mt][nt];
                float bb0 = bias[col], bb1 = bias[col + 1];
                if (r0 < NN) { float2 v = {cc[0] + d0 * bb0, cc[1] + d0 * bb1}; *(float2*)(Og + (size_t)r0 * C + col) = v; }
                if (r1 < NN) { float2 v = {cc[2] + d1 * bb0, cc[3] + d1 * bb1}; *(float2*)(Og + (size_t)r1 * C + col) = v; }
            }
        }
    } else {
        // fused relu + L2 norm -> g_Hf (A-fragment order)
#pragma unroll
        for (int mt = 0; mt < 4; mt++) {
            int r0 = i0 + m0 + mt * 16 + gid;
            int r1 = r0 + 8;
            int l0 = m0 + mt * 16 + gid, l1 = l0 + 8;
            float d0 = (r0 < NN) ? g_deg[r0] : 0.f;
            float d1 = (r1 < NN) ? g_deg[r1] : 0.f;
            float ss0 = 0.f, ss1 = 0.f;
#pragma unroll
            for (int nt = 0; nt < 4; nt++) {
                int col = n0 + nt * 8 + 2 * tig;
                float* cc = acc[mt][nt];
                float bb0 = bias[col], bb1 = bias[col + 1];
                cc[0] = fmaxf(cc[0] + d0 * bb0, 0.f);
                cc[1] = fmaxf(cc[1] + d0 * bb1, 0.f);
                cc[2] = fmaxf(cc[2] + d1 * bb0, 0.f);
                cc[3] = fmaxf(cc[3] + d1 * bb1, 0.f);
                ss0 += cc[0] * cc[0] + cc[1] * cc[1];
                ss1 += cc[2] * cc[2] + cc[3] * cc[3];
            }
            atomicAdd(&rowss[l0], ss0);
            atomicAdd(&rowss[l1], ss1);
        }
        __syncthreads();
#pragma unroll
        for (int mt = 0; mt < 4; mt++) {
            int r0 = i0 + m0 + mt * 16 + gid;
            int r1 = r0 + 8;
            int l0 = m0 + mt * 16 + gid, l1 = l0 + 8;
            float inv0 = 1.f / fmaxf(sqrtf(rowss[l0]), 1e-12f);
            float inv1 = 1.f / fmaxf(sqrtf(rowss[l1]), 1e-12f);
#pragma unroll
            for (int nt = 0; nt < 4; nt++) {
                int col = n0 + nt * 8 + 2 * tig;
                int P = (col >> 1);
                float* cc = acc[mt][nt];
                unsigned h, l;
                if (r0 < NN) {
                    split2(cc[0] * inv0, cc[1] * inv0, h, l);
                    int ih = a_off(r0, P, 0);
                    g_Hf[ih] = h; g_Hf[ih + 128] = l;
                }
                if (r1 < NN) {
                    split2(cc[2] * inv1, cc[3] * inv1, h, l);
                    int ih = a_off(r1, P, 0);
                    g_Hf[ih] = h; g_Hf[ih + 128] = l;
                }
            }
        }
    }
}

// ---------------- CSR edge aggregate + BN affine + fragment write ----------
__global__ __launch_bounds__(256) void edge_csr_kernel(int layer) {
    int node = (blockIdx.x * blockDim.x + threadIdx.x) >> 5;
    int lane = threadIdx.x & 31;
    if (node >= NN) return;
    int s0 = g_rowp[node], s1 = g_rowp[node + 1];
    float4 a = ((const float4*)(g_A + (size_t)node * C))[lane];
    float4 acc = make_float4(0.f, 0.f, 0.f, 0.f);
    int e = s0;
    for (; e + 3 < s1; e += 4) {
        int i0 = g_csr[e], i1 = g_csr[e + 1], i2 = g_csr[e + 2], i3 = g_csr[e + 3];
        float4 b0 = ((const float4*)(g_B + (size_t)i0 * C))[lane];
        float4 b1 = ((const float4*)(g_B + (size_t)i1 * C))[lane];
        float4 b2 = ((const float4*)(g_B + (size_t)i2 * C))[lane];
        float4 b3 = ((const float4*)(g_B + (size_t)i3 * C))[lane];
        acc.x += fmaxf(a.x + b0.x, 0.f) + fmaxf(a.x + b1.x, 0.f)
               + fmaxf(a.x + b2.x, 0.f) + fmaxf(a.x + b3.x, 0.f);
        acc.y += fmaxf(a.y + b0.y, 0.f) + fmaxf(a.y + b1.y, 0.f)
               + fmaxf(a.y + b2.y, 0.f) + fmaxf(a.y + b3.y, 0.f);
        acc.z += fmaxf(a.z + b0.z, 0.f) + fmaxf(a.z + b1.z, 0.f)
               + fmaxf(a.z + b2.z, 0.f) + fmaxf(a.z + b3.z, 0.f);
        acc.w += fmaxf(a.w + b0.w, 0.f) + fmaxf(a.w + b1.w, 0.f)
               + fmaxf(a.w + b2.w, 0.f) + fmaxf(a.w + b3.w, 0.f);
    }
    for (; e < s1; e++) {
        int sa = g_csr[e];
        float4 b0 = ((const float4*)(g_B + (size_t)sa * C))[lane];
        acc.x += fmaxf(a.x + b0.x, 0.f);
        acc.y += fmaxf(a.y + b0.y, 0.f);
        acc.z += fmaxf(a.z + b0.z, 0.f);
        acc.w += fmaxf(a.w + b0.w, 0.f);
    }
    float dg = (float)(s1 - s0);
    float4 sc = ((const float4*)(g_s[layer]))[lane];
    float4 cv = ((const float4*)(g_c[layer]))[lane];
    acc.x = sc.x * acc.x + dg * cv.x;
    acc.y = sc.y * acc.y + dg * cv.y;
    acc.z = sc.z * acc.z + dg * cv.z;
    acc.w = sc.w * acc.w + dg * cv.w;
    int P0 = lane * 2, P1 = lane * 2 + 1;
    unsigned h, l;
    split2(acc.x, acc.y, h, l);
    int ih = a_off(node, P0, 0);
    g_Rf[ih] = h; g_Rf[ih + 128] = l;
    split2(acc.z, acc.w, h, l);
    ih = a_off(node, P1, 0);
    g_Rf[ih] = h; g_Rf[ih + 128] = l;
    if (lane == 0) g_deg[node] = dg;
}

// ---------------- launch ----------------------------------------------------
extern "C" void kernel_launch(void* const* d_in, const int* in_sizes, int n_in,
                              void* d_out, int out_size) {
    const float* x   = (const float*)d_in[0];
    const void*  ei  = d_in[1];
    const float* w1a = (const float*)d_in[2];
    const float* b1a = (const float*)d_in[3];
    const float* g1  = (const float*)d_in[4];
    const float* be1 = (const float*)d_in[5];
    const float* rm1 = (const float*)d_in[6];
    const float* rv1 = (const float*)d_in[7];
    const float* w1b = (const float*)d_in[8];
    const float* b1b = (const float*)d_in[9];
    const float* w2a = (const float*)d_in[10];
    const float* b2a = (const float*)d_in[11];
    const float* g2  = (const float*)d_in[12];
    const float* be2 = (const float*)d_in[13];
    const float* rm2 = (const float*)d_in[14];
    const float* rv2 = (const float*)d_in[15];
    const float* w2b = (const float*)d_in[16];
    const float* b2b = (const float*)d_in[17];
    float* out = (float*)d_out;

    const int ROWB = NB_BLK;
    const int EB   = (NN * 32 + 255) / 256;     // 6250
    const int CXB  = (NB_BLK * 2048 + 255) / 256;

    unsigned *Wf0, *Wf1, *Wbf0, *Wbf1;
    unsigned *Xf, *Hf, *Rf;
    cudaGetSymbolAddress((void**)&Xf, g_Xf);
    cudaGetSymbolAddress((void**)&Hf, g_Hf);
    cudaGetSymbolAddress((void**)&Rf, g_Rf);
    cudaGetSymbolAddress((void**)&Wf0, g_Wf);
    Wf1 = Wf0 + 2 * 16384;
    cudaGetSymbolAddress((void**)&Wbf0, g_Wbf);
    Wbf1 = Wbf0 + 16384;

    prep_all<<<256, 256>>>(w1a, w2a, w1b, w2b, g1, be1, rm1, rv1, g2, be2, rm2, rv2); // 0
    detect_kernel<<<1, 32>>>(ei);                                                     // 1
    conv_x<<<CXB, 256>>>(x);                                                          // 2
    // layer-1 AB GEMM at stream index 3 -> profiled by ncu
    mma_gemm<<<dim3(ROWB, 2), 256>>>(Xf, Wf0, b1a, nullptr, 0);                       // 3 -> g_A,g_B
    hist_kernel<<<(EE + 255) / 256, 256>>>(ei);                                       // 4
    scan_local<<<SCAN_NB, 256>>>();                                                   // 5
    scan_bsum<<<1, 256>>>();                                                          // 6
    scan_add<<<SCAN_NB, 256>>>();                                                     // 7
    scatter_kernel<<<(EE + 255) / 256, 256>>>(ei);                                    // 8

    // ---- layer 1 ----
    edge_csr_kernel<<<EB, 256>>>(0);                                                  // -> g_Rf,g_deg
    mma_gemm<<<dim3(ROWB, 1), 256>>>(Rf, Wbf0, b1b, nullptr, 2);                      // -> g_Hf

    // ---- layer 2 ----
    mma_gemm<<<dim3(ROWB, 2), 256>>>(Hf, Wf1, b2a, nullptr, 0);                       // g_Hf -> g_A,g_B
    edge_csr_kernel<<<EB, 256>>>(1);
    mma_gemm<<<dim3(ROWB, 1), 256>>>(Rf, Wbf1, b2b, out, 1);                          // -> d_out
}